// round 10
// baseline (speedup 1.0000x reference)
#include <cuda_runtime.h>

#define N_NODES 48
#define N_EDGES 192
#define DIM     1024
#define NN      (N_NODES * N_NODES)   // 2304
#define EE      (N_EDGES * N_EDGES)   // 36864
#define OUT_DIM NN                    // 2304
#define SPLITK  16
#define KC      (DIM / SPLITK)        // 64
#define N4      ((OUT_DIM * OUT_DIM) / 4)   // 1,327,104 float4
#define GEMM_BLOCKS 144               // 3 x 3 x 16
#define MP_BLOCKS   96
#define POST_BLOCKS (GEMM_BLOCKS + MP_BLOCKS)  // 240
#define PRE_BLOCKS  512               // 4 coeff rows each
#define PRE_THREADS 256

// Scratch (no cudaMalloc allowed)
__device__ float g_cn[DIM];
__device__ float g_ce[DIM];
__device__ float g_MePart[SPLITK][EE];
// Per-tile cumulative ticket counters (never reset -> replay-safe: each
// launch adds exactly SPLITK arrivals per tile, so exactly one block per
// tile per launch sees (ticket+1) % SPLITK == 0 and becomes the reducer).
__device__ unsigned g_tile_tick[9];

__device__ __forceinline__ float softplus_act(float x) {
    // relu(softplus(x) - 0.5)
    float sp = (x > 20.f) ? x : log1pf(expf(x));
    float v = sp - 0.5f;
    return v > 0.f ? v : 0.f;
}

// ---------------------------------------------------------------------------
// Kernel 1: coeff = tanh(W @ gw + b) (4 rows per block) + full 21MB zero-fill.
// Weight loads (4 LDG.128/thread) and zero stores interleave; the 21MB of
// stores drain to L2 while the weight loads are in flight.
// ---------------------------------------------------------------------------
__global__ void __launch_bounds__(PRE_THREADS)
k_pre(const float* __restrict__ Wn, const float* __restrict__ bn,
      const float* __restrict__ We, const float* __restrict__ be,
      const float* __restrict__ gw, float4* __restrict__ out4) {
    __shared__ float sred[32];
    int t = threadIdx.x;
    int lane = t & 31, warp = t >> 5;
    int r0 = blockIdx.x * 4;                 // 0..2044, never straddles Wn/We
    const float* W;
    const float* bias;
    float* outp;
    int rr;
    if (r0 < DIM) { W = Wn; bias = bn; outp = g_cn; rr = r0; }
    else          { W = We; bias = be; outp = g_ce; rr = r0 - DIM; }

    const float4* p = (const float4*)(W + rr * DIM);  // row stride = 256 float4
    float4 a0 = p[t], a1 = p[256 + t], a2 = p[512 + t], a3 = p[768 + t];
    float4 g = ((const float4*)gw)[t];

    // zero-fill output (independent of the loads above)
    {
        float4 z = make_float4(0.f, 0.f, 0.f, 0.f);
        for (int i = blockIdx.x * PRE_THREADS + t; i < N4;
             i += PRE_BLOCKS * PRE_THREADS)
            out4[i] = z;
    }

    float s0 = a0.x * g.x + a0.y * g.y + a0.z * g.z + a0.w * g.w;
    float s1 = a1.x * g.x + a1.y * g.y + a1.z * g.z + a1.w * g.w;
    float s2 = a2.x * g.x + a2.y * g.y + a2.z * g.z + a2.w * g.w;
    float s3 = a3.x * g.x + a3.y * g.y + a3.z * g.z + a3.w * g.w;
#pragma unroll
    for (int o = 16; o; o >>= 1) {
        s0 += __shfl_xor_sync(0xffffffffu, s0, o);
        s1 += __shfl_xor_sync(0xffffffffu, s1, o);
        s2 += __shfl_xor_sync(0xffffffffu, s2, o);
        s3 += __shfl_xor_sync(0xffffffffu, s3, o);
    }
    if (lane == 0) {
        sred[0 * 8 + warp] = s0;
        sred[1 * 8 + warp] = s1;
        sred[2 * 8 + warp] = s2;
        sred[3 * 8 + warp] = s3;
    }
    __syncthreads();
    if (t < 4) {
        float s = 0.f;
#pragma unroll
        for (int j = 0; j < 8; j++) s += sred[t * 8 + j];
        outp[rr + t] = tanhf(s + bias[rr + t]);
    }
}

// ---------------------------------------------------------------------------
// Kernel 2: blocks 0..143  -> Me split-K GEMM partial; the LAST block to
//           finish within each of the 9 output tiles reduces that tile's 16
//           partials, activates, and scatter-adds its 4096 edge pairs.
//           blocks 144..239 -> Mp, diagonal added directly (M pre-zeroed).
// No spinning, no grid barrier, no co-residency requirement.
// ---------------------------------------------------------------------------
__global__ void __launch_bounds__(256, 2)
k_post(const float* __restrict__ ef1, const float* __restrict__ ef2,
       const float* __restrict__ x1, const float* __restrict__ x2,
       const int* __restrict__ ei1, const int* __restrict__ ei2,
       float* __restrict__ M) {
    int t = threadIdx.x;
    int b = blockIdx.x;

    if (b < GEMM_BLOCKS) {
        // ---- Me GEMM partial: C[m,n] = sum_k ef1[m,k]*ce[k]*ef2[n,k]
        __shared__ float4 As[16][17];   // [kk][rowgroup]
        __shared__ float4 Bs[16][17];
        __shared__ int s_last;
        float* Asf = (float*)As;        // row stride 68 floats
        float* Bsf = (float*)Bs;

        int tx = t & 15, ty = t >> 4;
        int bx = b % 3;
        int by = (b / 3) % 3;
        int kz = b / 9;                 // 0..15
        int tile = by * 3 + bx;         // 0..8
        int lr = t >> 2;                // 0..63 (tile row this thread loads)
        int lc = (t & 3) * 4;           // 0,4,8,12 (k-chunk base)
        float acc[4][4] = {};
        int k0 = kz * KC;
        const float* Arow = ef1 + (by * 64 + lr) * DIM;
        const float* Brow = ef2 + (bx * 64 + lr) * DIM;

        for (int kb = k0; kb < k0 + KC; kb += 16) {
            float4 c4 = *(const float4*)(g_ce + kb + lc);
            float4 a4 = *(const float4*)(Arow + kb + lc);
            float4 b4 = *(const float4*)(Brow + kb + lc);
            a4.x *= c4.x; a4.y *= c4.y; a4.z *= c4.z; a4.w *= c4.w;
            Asf[(lc + 0) * 68 + lr] = a4.x;
            Asf[(lc + 1) * 68 + lr] = a4.y;
            Asf[(lc + 2) * 68 + lr] = a4.z;
            Asf[(lc + 3) * 68 + lr] = a4.w;
            Bsf[(lc + 0) * 68 + lr] = b4.x;
            Bsf[(lc + 1) * 68 + lr] = b4.y;
            Bsf[(lc + 2) * 68 + lr] = b4.z;
            Bsf[(lc + 3) * 68 + lr] = b4.w;
            __syncthreads();
#pragma unroll
            for (int kk = 0; kk < 16; kk++) {
                float4 av = As[kk][ty];
                float4 bv = Bs[kk][tx];
                float a[4] = {av.x, av.y, av.z, av.w};
                float bb[4] = {bv.x, bv.y, bv.z, bv.w};
#pragma unroll
                for (int j = 0; j < 4; j++)
#pragma unroll
                    for (int i = 0; i < 4; i++)
                        acc[j][i] += a[j] * bb[i];
            }
            __syncthreads();
        }

        float* outp = g_MePart[kz];
#pragma unroll
        for (int j = 0; j < 4; j++) {
            int m = by * 64 + 4 * ty + j;
            int n = bx * 64 + 4 * tx;
            *(float4*)(outp + m * N_EDGES + n) =
                make_float4(acc[j][0], acc[j][1], acc[j][2], acc[j][3]);
        }

        // ---- ticket: last finisher of this tile does the reduce+scatter
        __syncthreads();
        if (t == 0) {
            __threadfence();                       // publish partial
            unsigned tk = atomicAdd(&g_tile_tick[tile], 1u);
            s_last = (((tk + 1u) % (unsigned)SPLITK) == 0u) ? 1 : 0;
        }
        __syncthreads();
        if (s_last) {
            __threadfence();                       // acquire others' partials
            // 64x64 outputs = 1024 groups of 4 consecutive n; 4 groups/thread.
            // value for (m, n): Me.flat[m*192+n] ->
            //   M[ei2h[m]*48+ei1h[n], ei2t[m]*48+ei1t[n]] += act(.)
            for (int g = t; g < 1024; g += 256) {
                int m  = by * 64 + (g >> 4);
                int n0 = bx * 64 + (g & 15) * 4;
                int idx = m * N_EDGES + n0;
                float4 s = make_float4(0.f, 0.f, 0.f, 0.f);
#pragma unroll
                for (int z = 0; z < SPLITK; z++) {
                    float4 p = *(const float4*)(g_MePart[z] + idx);
                    s.x += p.x; s.y += p.y; s.z += p.z; s.w += p.w;
                }
                int rb = ei2[m] * N_NODES;             // head2*48
                int cb = ei2[N_EDGES + m] * N_NODES;   // tail2*48
                float v0 = softplus_act(s.x);
                float v1 = softplus_act(s.y);
                float v2 = softplus_act(s.z);
                float v3 = softplus_act(s.w);
                if (v0 > 0.f)
                    atomicAdd(M + (size_t)(rb + ei1[n0 + 0]) * OUT_DIM
                                + cb + ei1[N_EDGES + n0 + 0], v0);
                if (v1 > 0.f)
                    atomicAdd(M + (size_t)(rb + ei1[n0 + 1]) * OUT_DIM
                                + cb + ei1[N_EDGES + n0 + 1], v1);
                if (v2 > 0.f)
                    atomicAdd(M + (size_t)(rb + ei1[n0 + 2]) * OUT_DIM
                                + cb + ei1[N_EDGES + n0 + 2], v2);
                if (v3 > 0.f)
                    atomicAdd(M + (size_t)(rb + ei1[n0 + 3]) * OUT_DIM
                                + cb + ei1[N_EDGES + n0 + 3], v3);
            }
        }
    } else {
        // ---- Mp: 768 warps, 3 outputs per warp; diagonal added directly.
        int lane = t & 31, warp = t >> 5;
        int w = (b - GEMM_BLOCKS) * 8 + warp;   // 0..767
        int idx0 = w * 3;
        int m = idx0 / N_NODES, n0 = idx0 % N_NODES;  // same m across the 3
        const float4* A  = (const float4*)(x1 + m * DIM);
        const float4* B0 = (const float4*)(x2 + n0 * DIM);
        const float4* C  = (const float4*)g_cn;
        float s0 = 0.f, s1 = 0.f, s2 = 0.f;
#pragma unroll
        for (int i = 0; i < 8; i++) {
            int k = i * 32 + lane;
            float4 a = A[k], c = C[k];
            a.x *= c.x; a.y *= c.y; a.z *= c.z; a.w *= c.w;
            float4 b0 = B0[k], b1 = B0[256 + k], b2 = B0[512 + k];
            s0 += a.x * b0.x + a.y * b0.y + a.z * b0.z + a.w * b0.w;
            s1 += a.x * b1.x + a.y * b1.y + a.z * b1.z + a.w * b1.w;
            s2 += a.x * b2.x + a.y * b2.y + a.z * b2.z + a.w * b2.w;
        }
#pragma unroll
        for (int o = 16; o; o >>= 1) {
            s0 += __shfl_xor_sync(0xffffffffu, s0, o);
            s1 += __shfl_xor_sync(0xffffffffu, s1, o);
            s2 += __shfl_xor_sync(0xffffffffu, s2, o);
        }
        if (lane == 0) {
            // M[a, a] += Mp.flat[a]  (M zeroed by k_pre)
            atomicAdd(M + (size_t)(idx0 + 0) * (OUT_DIM + 1), softplus_act(s0));
            atomicAdd(M + (size_t)(idx0 + 1) * (OUT_DIM + 1), softplus_act(s1));
            atomicAdd(M + (size_t)(idx0 + 2) * (OUT_DIM + 1), softplus_act(s2));
        }
    }
}

extern "C" void kernel_launch(void* const* d_in, const int* in_sizes, int n_in,
                              void* d_out, int out_size) {
    const float* x1  = (const float*)d_in[0];
    const float* x2  = (const float*)d_in[1];
    const float* ef1 = (const float*)d_in[2];
    const float* ef2 = (const float*)d_in[3];
    const float* gw  = (const float*)d_in[4];
    const float* Wn  = (const float*)d_in[5];
    const float* bn  = (const float*)d_in[6];
    const float* We  = (const float*)d_in[7];
    const float* be  = (const float*)d_in[8];
    const int*   ei1 = (const int*)d_in[9];
    const int*   ei2 = (const int*)d_in[10];
    float* M = (float*)d_out;

    k_pre<<<PRE_BLOCKS, PRE_THREADS>>>(Wn, bn, We, be, gw, (float4*)M);
    k_post<<<POST_BLOCKS, 256>>>(ef1, ef2, x1, x2, ei1, ei2, M);
}

// round 11
// speedup vs baseline: 1.2262x; 1.2262x over previous
#include <cuda_runtime.h>

#define N_NODES 48
#define N_EDGES 192
#define DIM     1024
#define NN      (N_NODES * N_NODES)   // 2304
#define EE      (N_EDGES * N_EDGES)   // 36864
#define OUT_DIM NN                    // 2304
#define SPLITK  32
#define KC      (DIM / SPLITK)        // 32
#define N4      ((OUT_DIM * OUT_DIM) / 4)   // 1,327,104 float4
#define GEMM_BLOCKS (9 * SPLITK)      // 288
#define MP_BLOCKS   96
#define MAIN_BLOCKS (GEMM_BLOCKS + MP_BLOCKS)  // 384
#define PRE_BLOCKS  512               // 4 coeff rows each
#define PRE_THREADS 256

// Scratch (no cudaMalloc allowed)
__device__ float g_cn[DIM];
__device__ float g_ce[DIM];
__device__ float g_MePart[SPLITK][EE];   // 4.7 MB, L2-resident

__device__ __forceinline__ float softplus_act(float x) {
    // relu(softplus(x) - 0.5)
    float sp = (x > 20.f) ? x : log1pf(expf(x));
    float v = sp - 0.5f;
    return v > 0.f ? v : 0.f;
}

// ---------------------------------------------------------------------------
// Kernel 1: coeff = tanh(W @ gw + b) (4 rows per block) + full 21MB zero-fill.
// 4 independent LDG.128/thread for weights; zero stores drain to L2 while
// the weight loads are in flight.
// ---------------------------------------------------------------------------
__global__ void __launch_bounds__(PRE_THREADS)
k_pre(const float* __restrict__ Wn, const float* __restrict__ bn,
      const float* __restrict__ We, const float* __restrict__ be,
      const float* __restrict__ gw, float4* __restrict__ out4) {
    __shared__ float sred[32];
    int t = threadIdx.x;
    int lane = t & 31, warp = t >> 5;
    int r0 = blockIdx.x * 4;                 // 0..2044, never straddles Wn/We
    const float* W;
    const float* bias;
    float* outp;
    int rr;
    if (r0 < DIM) { W = Wn; bias = bn; outp = g_cn; rr = r0; }
    else          { W = We; bias = be; outp = g_ce; rr = r0 - DIM; }

    const float4* p = (const float4*)(W + rr * DIM);  // row stride = 256 float4
    float4 a0 = p[t], a1 = p[256 + t], a2 = p[512 + t], a3 = p[768 + t];
    float4 g = ((const float4*)gw)[t];

    // zero-fill output (independent of the loads above)
    {
        float4 z = make_float4(0.f, 0.f, 0.f, 0.f);
        for (int i = blockIdx.x * PRE_THREADS + t; i < N4;
             i += PRE_BLOCKS * PRE_THREADS)
            out4[i] = z;
    }

    float s0 = a0.x * g.x + a0.y * g.y + a0.z * g.z + a0.w * g.w;
    float s1 = a1.x * g.x + a1.y * g.y + a1.z * g.z + a1.w * g.w;
    float s2 = a2.x * g.x + a2.y * g.y + a2.z * g.z + a2.w * g.w;
    float s3 = a3.x * g.x + a3.y * g.y + a3.z * g.z + a3.w * g.w;
#pragma unroll
    for (int o = 16; o; o >>= 1) {
        s0 += __shfl_xor_sync(0xffffffffu, s0, o);
        s1 += __shfl_xor_sync(0xffffffffu, s1, o);
        s2 += __shfl_xor_sync(0xffffffffu, s2, o);
        s3 += __shfl_xor_sync(0xffffffffu, s3, o);
    }
    if (lane == 0) {
        sred[0 * 8 + warp] = s0;
        sred[1 * 8 + warp] = s1;
        sred[2 * 8 + warp] = s2;
        sred[3 * 8 + warp] = s3;
    }
    __syncthreads();
    if (t < 4) {
        float s = 0.f;
#pragma unroll
        for (int j = 0; j < 8; j++) s += sred[t * 8 + j];
        outp[rr + t] = tanhf(s + bias[rr + t]);
    }
}

// ---------------------------------------------------------------------------
// Kernel 2: blocks 0..287  -> Me split-K(32) GEMM partials, 64x64 tile,
//                            k-major smem, contiguous 4x4 C tile per thread.
//                            2 blocks/SM -> 4 warps/SMSP for latency hiding.
//           blocks 288..383 -> Mp (48x48), diagonal added directly to M.
// ---------------------------------------------------------------------------
__global__ void __launch_bounds__(256, 2)
k_main(const float* __restrict__ ef1, const float* __restrict__ ef2,
       const float* __restrict__ x1, const float* __restrict__ x2,
       float* __restrict__ M) {
    int t = threadIdx.x;
    int b = blockIdx.x;

    if (b < GEMM_BLOCKS) {
        // ---- Me GEMM partial: C[m,n] = sum_k ef1[m,k]*ce[k]*ef2[n,k]
        __shared__ float4 As[16][17];   // [kk][rowgroup]
        __shared__ float4 Bs[16][17];
        float* Asf = (float*)As;        // row stride 68 floats
        float* Bsf = (float*)Bs;

        int tx = t & 15, ty = t >> 4;
        int bx = b % 3;
        int by = (b / 3) % 3;
        int kz = b / 9;                 // 0..31
        int lr = t >> 2;                // 0..63 (tile row this thread loads)
        int lc = (t & 3) * 4;           // 0,4,8,12 (k-chunk base)
        float acc[4][4] = {};
        int k0 = kz * KC;
        const float* Arow = ef1 + (by * 64 + lr) * DIM;
        const float* Brow = ef2 + (bx * 64 + lr) * DIM;

#pragma unroll
        for (int kb = k0; kb < k0 + KC; kb += 16) {
            float4 c4 = *(const float4*)(g_ce + kb + lc);
            float4 a4 = *(const float4*)(Arow + kb + lc);
            float4 b4 = *(const float4*)(Brow + kb + lc);
            a4.x *= c4.x; a4.y *= c4.y; a4.z *= c4.z; a4.w *= c4.w;
            Asf[(lc + 0) * 68 + lr] = a4.x;
            Asf[(lc + 1) * 68 + lr] = a4.y;
            Asf[(lc + 2) * 68 + lr] = a4.z;
            Asf[(lc + 3) * 68 + lr] = a4.w;
            Bsf[(lc + 0) * 68 + lr] = b4.x;
            Bsf[(lc + 1) * 68 + lr] = b4.y;
            Bsf[(lc + 2) * 68 + lr] = b4.z;
            Bsf[(lc + 3) * 68 + lr] = b4.w;
            __syncthreads();
#pragma unroll
            for (int kk = 0; kk < 16; kk++) {
                float4 av = As[kk][ty];
                float4 bv = Bs[kk][tx];
                float a[4] = {av.x, av.y, av.z, av.w};
                float bb[4] = {bv.x, bv.y, bv.z, bv.w};
#pragma unroll
                for (int j = 0; j < 4; j++)
#pragma unroll
                    for (int i = 0; i < 4; i++)
                        acc[j][i] += a[j] * bb[i];
            }
            __syncthreads();
        }

        float* outp = g_MePart[kz];
#pragma unroll
        for (int j = 0; j < 4; j++) {
            int m = by * 64 + 4 * ty + j;
            int n = bx * 64 + 4 * tx;
            *(float4*)(outp + m * N_EDGES + n) =
                make_float4(acc[j][0], acc[j][1], acc[j][2], acc[j][3]);
        }
    } else {
        // ---- Mp: 768 warps, 3 outputs per warp; diagonal added directly.
        int lane = t & 31, warp = t >> 5;
        int w = (b - GEMM_BLOCKS) * 8 + warp;   // 0..767
        int idx0 = w * 3;
        int m = idx0 / N_NODES, n0 = idx0 % N_NODES;  // same m across the 3
        const float4* A  = (const float4*)(x1 + m * DIM);
        const float4* B0 = (const float4*)(x2 + n0 * DIM);
        const float4* C  = (const float4*)g_cn;
        float s0 = 0.f, s1 = 0.f, s2 = 0.f;
#pragma unroll
        for (int i = 0; i < 8; i++) {
            int k = i * 32 + lane;
            float4 a = A[k], c = C[k];
            a.x *= c.x; a.y *= c.y; a.z *= c.z; a.w *= c.w;
            float4 b0 = B0[k], b1 = B0[256 + k], b2 = B0[512 + k];
            s0 += a.x * b0.x + a.y * b0.y + a.z * b0.z + a.w * b0.w;
            s1 += a.x * b1.x + a.y * b1.y + a.z * b1.z + a.w * b1.w;
            s2 += a.x * b2.x + a.y * b2.y + a.z * b2.z + a.w * b2.w;
        }
#pragma unroll
        for (int o = 16; o; o >>= 1) {
            s0 += __shfl_xor_sync(0xffffffffu, s0, o);
            s1 += __shfl_xor_sync(0xffffffffu, s1, o);
            s2 += __shfl_xor_sync(0xffffffffu, s2, o);
        }
        if (lane == 0) {
            // M[a, a] += Mp.flat[a]  (M zeroed by k_pre)
            atomicAdd(M + (size_t)(idx0 + 0) * (OUT_DIM + 1), softplus_act(s0));
            atomicAdd(M + (size_t)(idx0 + 1) * (OUT_DIM + 1), softplus_act(s1));
            atomicAdd(M + (size_t)(idx0 + 2) * (OUT_DIM + 1), softplus_act(s2));
        }
    }
}

// ---------------------------------------------------------------------------
// Kernel 3: reduce 32 split-K partials (32 independent LDG per thread),
// activate, scatter-add edge pairs into M.
// value for pair (j1,j2) is Me.flat[j2*192+j1]:
//   M[head2[j2]*48+head1[j1], tail2[j2]*48+tail1[j1]] += act(.)
// ---------------------------------------------------------------------------
__global__ void __launch_bounds__(128)
k_scatter(const int* __restrict__ ei1, const int* __restrict__ ei2,
          float* __restrict__ M) {
    int idx = blockIdx.x * 128 + threadIdx.x;   // 0..EE-1 (288 blocks)
    float s = 0.f;
#pragma unroll
    for (int z = 0; z < SPLITK; z++) s += g_MePart[z][idx];
    float v = softplus_act(s);
    if (v > 0.f) {
        int j2 = idx / N_EDGES;   // row of Me flat view
        int j1 = idx % N_EDGES;   // col of Me flat view
        int r = ei2[j2] * N_NODES + ei1[j1];                      // heads
        int c = ei2[N_EDGES + j2] * N_NODES + ei1[N_EDGES + j1];  // tails
        atomicAdd(M + (size_t)r * OUT_DIM + c, v);
    }
}

extern "C" void kernel_launch(void* const* d_in, const int* in_sizes, int n_in,
                              void* d_out, int out_size) {
    const float* x1  = (const float*)d_in[0];
    const float* x2  = (const float*)d_in[1];
    const float* ef1 = (const float*)d_in[2];
    const float* ef2 = (const float*)d_in[3];
    const float* gw  = (const float*)d_in[4];
    const float* Wn  = (const float*)d_in[5];
    const float* bn  = (const float*)d_in[6];
    const float* We  = (const float*)d_in[7];
    const float* be  = (const float*)d_in[8];
    const int*   ei1 = (const int*)d_in[9];
    const int*   ei2 = (const int*)d_in[10];
    float* M = (float*)d_out;

    k_pre<<<PRE_BLOCKS, PRE_THREADS>>>(Wn, bn, We, be, gw, (float4*)M);
    k_main<<<MAIN_BLOCKS, 256>>>(ef1, ef2, x1, x2, M);
    k_scatter<<<EE / 128, 128>>>(ei1, ei2, M);
}